// round 12
// baseline (speedup 1.0000x reference)
#include <cuda_runtime.h>

// out[i,p] = sum_{m,n} A[i,m] * B[i,n] * C[m,n,p]   (M1=M2=MP=5)
//
// Round-12 = round-11 body EXACTLY (EPT=1, front-batched LDG.32, padded
// constant C with LDC.128+LDC.32 columns, STG.32 out) with the occupancy
// cap raised to the architectural max:
//   __launch_bounds__(256, 8) -> 32-reg cap -> 8 CTAs/SM = 64 warps.
// Round-11 measured ~28 live regs for this body (compiled at 40 under a
// 42 cap, no spill), so 32 has genuine slack — unlike the failed 48-cap
// rounds whose bodies needed 45-60. 48 warps gave occ 61.6%, DRAM 72%,
// issue 67%; full warp occupancy should push both toward their roofs
// (~114-122us).

#define M1 5
#define M2 5
#define MP 5
#define TPB 256
#define CPAD_FLOATS (M1 * MP * 8)      // 200

__constant__ float cCp[CPAD_FLOATS];   // cCp[(m*5+p)*8 + n], n in 0..4, padded
__device__ float g_scratch[CPAD_FLOATS];

__global__ void transpose_C_kernel(const float* __restrict__ C) {
    int idx = threadIdx.x;             // one block of 256 covers 200 slots
    if (idx < CPAD_FLOATS) {
        int m   = idx / (MP * 8);
        int rem = idx % (MP * 8);
        int p   = rem / 8;
        int n   = rem % 8;
        g_scratch[idx] = (n < M2) ? C[(m * M2 + n) * MP + p] : 0.0f;
    }
}

__global__ __launch_bounds__(TPB, 8)
void cg_combine_kernel(const float* __restrict__ A,
                       const float* __restrict__ B,
                       float* __restrict__ out,
                       long long n_edges)
{
    long long e = (long long)blockIdx.x * TPB + threadIdx.x;
    if (e >= n_edges) return;

    size_t base = (size_t)e * 5;

    // ---- front-batched loads: 10x LDG.32 ----
    const float* pa = A + base;
    const float* pb = B + base;
    float a0 = __ldcs(pa + 0), a1 = __ldcs(pa + 1), a2 = __ldcs(pa + 2),
          a3 = __ldcs(pa + 3), a4 = __ldcs(pa + 4);
    float b0 = __ldcs(pb + 0), b1 = __ldcs(pb + 1), b2 = __ldcs(pb + 2),
          b3 = __ldcs(pb + 3), b4 = __ldcs(pb + 4);

    float acc[MP];
#pragma unroll
    for (int p = 0; p < MP; p++) acc[p] = 0.0f;

    float am;
#pragma unroll
    for (int m = 0; m < M1; m++) {
        switch (m) {                    // keep a* as scalars, not an array
            case 0: am = a0; break;
            case 1: am = a1; break;
            case 2: am = a2; break;
            case 3: am = a3; break;
            default: am = a4; break;
        }
#pragma unroll
        for (int p = 0; p < MP; p++) {
            // C column (m, :, p): LDC.128 + LDC.32 from padded constant
            const float4 c03 =
                *reinterpret_cast<const float4*>(&cCp[(m * MP + p) * 8]);
            const float  c4  = cCp[(m * MP + p) * 8 + 4];

            float d = c03.x * b0;
            d = fmaf(b1, c03.y, d);
            d = fmaf(b2, c03.z, d);
            d = fmaf(b3, c03.w, d);
            d = fmaf(b4, c4,    d);

            acc[p] = fmaf(am, d, acc[p]);
        }
    }

    float* po = out + base;
#pragma unroll
    for (int p = 0; p < MP; p++) __stcs(po + p, acc[p]);
}

extern "C" void kernel_launch(void* const* d_in, const int* in_sizes, int n_in,
                              void* d_out, int out_size)
{
    const float* A = (const float*)d_in[0];
    const float* B = (const float*)d_in[1];
    const float* C = (const float*)d_in[2];
    float* out = (float*)d_out;

    // Prep: pad-transpose C into __device__ scratch, then copy into the
    // constant bank. Graph-capturable stream-0 nodes; stream order makes the
    // constant data visible to the main kernel.
    transpose_C_kernel<<<1, TPB>>>(C);
    void* scratch_ptr = nullptr;
    cudaGetSymbolAddress(&scratch_ptr, g_scratch);
    cudaMemcpyToSymbolAsync(cCp, scratch_ptr, CPAD_FLOATS * sizeof(float), 0,
                            cudaMemcpyDeviceToDevice, 0);

    long long n_edges = (long long)in_sizes[0] / M1;
    int blocks = (int)((n_edges + TPB - 1) / TPB);

    cg_combine_kernel<<<blocks, TPB>>>(A, B, out, n_edges);
}

// round 14
// speedup vs baseline: 1.2238x; 1.2238x over previous
#include <cuda_runtime.h>
#include <cstdint>

// out[i,p] = sum_{m,n} A[i,m] * B[i,n] * C[m,n,p]   (M1=M2=MP=5)
//
// Round-14 = round-13 (p-axis packed FFMA2, pre-packed constant C, round-11
// occupancy config: 42-reg cap, 6 CTAs/SM = 48 warps) with the epilogue
// fixed: out + e*5 is only 4B-aligned for odd e, so acc pairs are unpacked
// (register-pair mov.b64, ~free) and stored as 5 scalar STG.32 — exactly
// round-11's store pattern. Round-13 trapped on misaligned STG.64.

#define M1 5
#define M2 5
#define MP 5
#define TPB 256
#define NPAIR 3                          // p-pairs: (0,1) (2,3) (4,zero)
// packed C: cCd[((m*3 + pr)*8 + n)*2 + lane], lane0=p_lo, lane1=p_hi
#define CPK_FLOATS (M1 * NPAIR * 8 * 2)  // 240

__constant__ __align__(16) float cCd[CPK_FLOATS];
__device__ __align__(16) float g_scratch[CPK_FLOATS];

typedef unsigned long long u64;

__device__ __forceinline__ u64 pack2(float lo, float hi) {
    u64 r; asm("mov.b64 %0, {%1, %2};" : "=l"(r) : "f"(lo), "f"(hi)); return r;
}
__device__ __forceinline__ void unpack2(u64 v, float& lo, float& hi) {
    asm("mov.b64 {%0, %1}, %2;" : "=f"(lo), "=f"(hi) : "l"(v));
}
__device__ __forceinline__ u64 fma2(u64 a, u64 b, u64 c) {
    u64 r; asm("fma.rn.f32x2 %0, %1, %2, %3;" : "=l"(r) : "l"(a), "l"(b), "l"(c)); return r;
}
__device__ __forceinline__ u64 mul2(u64 a, u64 b) {
    u64 r; asm("mul.rn.f32x2 %0, %1, %2;" : "=l"(r) : "l"(a), "l"(b)); return r;
}

__global__ void pack_C_kernel(const float* __restrict__ C) {
    int idx = threadIdx.x;               // 240 slots, one block of 256
    if (idx < CPK_FLOATS) {
        int lane = idx & 1;
        int q    = idx >> 1;             // (m*3 + pr)*8 + n
        int n    = q & 7;
        int mp   = q >> 3;               // m*3 + pr
        int pr   = mp % 3;
        int m    = mp / 3;
        int p    = pr * 2 + lane;        // p index (pr=2,lane=1 -> p=5: pad)
        float v  = 0.0f;
        if (n < M2 && p < MP) v = C[(m * M2 + n) * MP + p];
        g_scratch[idx] = v;
    }
}

__global__ __launch_bounds__(TPB, 6)
void cg_combine_kernel(const float* __restrict__ A,
                       const float* __restrict__ B,
                       float* __restrict__ out,
                       long long n_edges)
{
    long long e = (long long)blockIdx.x * TPB + threadIdx.x;
    if (e >= n_edges) return;

    size_t base = (size_t)e * 5;

    // ---- front-batched loads: 10x LDG.32 ----
    const float* pa = A + base;
    const float* pb = B + base;
    float a0 = __ldcs(pa + 0), a1 = __ldcs(pa + 1), a2 = __ldcs(pa + 2),
          a3 = __ldcs(pa + 3), a4 = __ldcs(pa + 4);
    float b0 = __ldcs(pb + 0), b1 = __ldcs(pb + 1), b2 = __ldcs(pb + 2),
          b3 = __ldcs(pb + 3), b4 = __ldcs(pb + 4);

    // duplicate b into packed pairs (persistent, 5 x u64)
    u64 bp0 = pack2(b0, b0), bp1 = pack2(b1, b1), bp2 = pack2(b2, b2),
        bp3 = pack2(b3, b3), bp4 = pack2(b4, b4);

    u64 acc[NPAIR];
#pragma unroll
    for (int i = 0; i < NPAIR; i++) acc[i] = 0ULL;

#pragma unroll
    for (int m = 0; m < M1; m++) {
        float am;
        switch (m) {
            case 0: am = a0; break;
            case 1: am = a1; break;
            case 2: am = a2; break;
            case 3: am = a3; break;
            default: am = a4; break;
        }
        u64 amp = pack2(am, am);         // transient pair

#pragma unroll
        for (int pr = 0; pr < NPAIR; pr++) {
            const float* col = &cCd[((m * NPAIR + pr) * 8) * 2];
            // 5 packed C values: 2x LDC.128 + 1x LDC.64 (const port, off L1)
            const ulonglong2 c01 = *reinterpret_cast<const ulonglong2*>(col + 0);
            const ulonglong2 c23 = *reinterpret_cast<const ulonglong2*>(col + 4);
            const u64        c4  = *reinterpret_cast<const u64*>(col + 8);

            u64 d = mul2(c01.x, bp0);
            d = fma2(bp1, c01.y, d);
            d = fma2(bp2, c23.x, d);
            d = fma2(bp3, c23.y, d);
            d = fma2(bp4, c4,    d);

            acc[pr] = fma2(amp, d, acc[pr]);
        }
    }

    // ---- epilogue: unpack (register-pair movs) + 5 scalar STG.32 ----
    float o0, o1, o2, o3, o4, dead;
    unpack2(acc[0], o0, o1);
    unpack2(acc[1], o2, o3);
    unpack2(acc[2], o4, dead);

    float* po = out + base;
    __stcs(po + 0, o0);
    __stcs(po + 1, o1);
    __stcs(po + 2, o2);
    __stcs(po + 3, o3);
    __stcs(po + 4, o4);
}

extern "C" void kernel_launch(void* const* d_in, const int* in_sizes, int n_in,
                              void* d_out, int out_size)
{
    const float* A = (const float*)d_in[0];
    const float* B = (const float*)d_in[1];
    const float* C = (const float*)d_in[2];
    float* out = (float*)d_out;

    // Prep: pack C into p-pairs in __device__ scratch, then copy into the
    // constant bank. Graph-capturable stream-0 nodes; stream order makes the
    // constant data visible to the main kernel.
    pack_C_kernel<<<1, TPB>>>(C);
    void* scratch_ptr = nullptr;
    cudaGetSymbolAddress(&scratch_ptr, g_scratch);
    cudaMemcpyToSymbolAsync(cCd, scratch_ptr, CPK_FLOATS * sizeof(float), 0,
                            cudaMemcpyDeviceToDevice, 0);

    long long n_edges = (long long)in_sizes[0] / M1;
    int blocks = (int)((n_edges + TPB - 1) / TPB);

    cg_combine_kernel<<<blocks, TPB>>>(A, B, out, n_edges);
}